// round 13
// baseline (speedup 1.0000x reference)
#include <cuda_runtime.h>
#include <cuda_bf16.h>
#include <math.h>

#define CROP 448
#define NR   56      // cells per side
#define NB   55      // blocks per side
#define B    48
#define IMG  512
#define TOP  32
#define QPR  112     // float4 quads per row (448/4)
#define SGW  456     // padded smem row width: col c at index c+4

// Cell histogram scratch: [b][cell_r][cell_c][bin]
__device__ float g_hist[(size_t)B * NR * NR * 9];
// Per-cell sum of squares: [b][cell_r][cell_c]
__device__ float g_cellss[(size_t)B * NR * NR];

__device__ __forceinline__ float fsqrt_approx(float x) {
    float r;
    asm("sqrt.approx.f32 %0, %1;" : "=f"(r) : "f"(x));
    return r;
}
__device__ __forceinline__ float frcp_approx(float x) {
    float r;
    asm("rcp.approx.f32 %0, %1;" : "=f"(r) : "f"(x));
    return r;
}

// No-op kernel: shifts the launch pattern to period 4 so ncu's "-s 5 -c 1"
// (launch index 5 mod 4 == 1) captures hog_cells_kernel instead of always
// landing on hog_blocks_kernel.
__global__ void noop_kernel() {}

// ---------------------------------------------------------------------------
// Kernel 1: gray -> sqrt -> gradients -> per-cell prefix histograms (+cell ss)
// grid: (NR, B), block: 448 threads (one per crop column)   [R12 verbatim]
// ---------------------------------------------------------------------------
__global__ __launch_bounds__(CROP) void hog_cells_kernel(
    const float* __restrict__ x, const float* __restrict__ coeffs,
    float* __restrict__ hist, float* __restrict__ cellss)
{
    __shared__ float sg[10][SGW];

    const int cr = blockIdx.x;       // cell row 0..55
    const int b  = blockIdx.y;
    const int c  = threadIdx.x;      // crop column 0..447
    const int r0 = cr * 8;

    const float c0 = coeffs[0], c1 = coeffs[1], c2 = coeffs[2];
    const float* base = x + (size_t)b * 3 * IMG * IMG;

    #pragma unroll
    for (int e = c; e < 10 * QPR; e += CROP) {
        int i = e / QPR;
        int q = e - i * QPR;
        int r = r0 - 1 + i;
        if (r < 0) r = -r;                        // -1 -> 1
        if (r > CROP - 1) r = 2 * (CROP - 1) - r; // 448 -> 446
        const float4* p = (const float4*)(base + (size_t)(r + TOP) * IMG + TOP) + q;
        float4 a0 = p[0];
        float4 a1 = p[(IMG * IMG) / 4];
        float4 a2 = p[(2 * IMG * IMG) / 4];
        float4 g;
        g.x = fsqrt_approx(fmaf(c0, a0.x, fmaf(c1, a1.x, c2 * a2.x)));
        g.y = fsqrt_approx(fmaf(c0, a0.y, fmaf(c1, a1.y, c2 * a2.y)));
        g.z = fsqrt_approx(fmaf(c0, a0.z, fmaf(c1, a1.z, c2 * a2.z)));
        g.w = fsqrt_approx(fmaf(c0, a0.w, fmaf(c1, a1.w, c2 * a2.w)));
        *((float4*)&sg[i][4 + q * 4]) = g;
        if (q == 0)       sg[i][3]   = g.y;   // col -1  := col 1
        if (q == QPR - 1) sg[i][452] = g.z;   // col 448 := col 446
    }
    __syncthreads();

    // cot(20k degrees), k = 1..8
    const float KT[8] = { 2.7474774f,  1.1917536f,  0.57735027f,  0.17632698f,
                         -0.17632698f, -0.57735027f, -1.1917536f, -2.7474774f};

    float vreg[10];
    #pragma unroll
    for (int i = 0; i < 10; i++) vreg[i] = sg[i][c + 4];

    // Prefix histogram: H[k] = sum of mag over pixels with angle >= 20k.
    float H[9];
    #pragma unroll
    for (int k = 0; k < 9; k++) H[k] = 0.f;

    #pragma unroll
    for (int i = 0; i < 8; i++) {
        float gr = vreg[i + 2] - vreg[i];
        float gc = sg[i + 1][c + 5] - sg[i + 1][c + 3];

        float mag = fsqrt_approx(fmaf(gr, gr, gc * gc));

        // Fold into upper half-plane. vv = |gr| is +0 on signed zeros so
        // w = +inf -> bin 0, matching the reference's 180 % 180 = 0.
        bool neg = (gr < 0.f) || (gr == 0.f && gc < 0.f);
        float u  = neg ? -gc : gc;
        float vv = fabsf(gr);

        // w = cot(angle); angle >= 20k  <=>  w <= cot(20k).
        float w = u * frcp_approx(vv);

        H[0] += mag;
        #pragma unroll
        for (int k = 0; k < 8; k++)
            if (w <= KT[k]) H[k + 1] += mag;
    }

    #pragma unroll
    for (int k = 0; k < 9; k++) {
        H[k] += __shfl_xor_sync(0xffffffffu, H[k], 1);
        H[k] += __shfl_xor_sync(0xffffffffu, H[k], 2);
        H[k] += __shfl_xor_sync(0xffffffffu, H[k], 4);
    }

    if ((c & 7) == 0) {
        int cell = c >> 3;
        size_t cidx = ((size_t)b * NR + cr) * NR + cell;
        float ss = 0.f;
        #pragma unroll
        for (int k = 0; k < 9; k++) {
            float hk = ((k < 8) ? (H[k] - H[k + 1]) : H[8]) * (1.0f / 64.0f);
            hist[cidx * 9 + k] = hk;
            ss += hk * hk;
        }
        cellss[cidx] = ss;
    }
}

// ---------------------------------------------------------------------------
// Kernel 2: L2-Hys block normalization. One CTA per (b, I) block-row.
// [R7 version verbatim — best measured 12.2us, frozen]
// ---------------------------------------------------------------------------
#define K2_THREADS 256
#define VSTRIDE 37          // padded per-block stride in vbuf (kills conflicts)

__global__ __launch_bounds__(K2_THREADS) void hog_blocks_kernel(
    const float* __restrict__ hist, const float* __restrict__ cellss,
    float* __restrict__ out)
{
    __shared__ float sh[2 * NR * 9];      // hist rows I, I+1 (1008)
    __shared__ float scs[2 * NR];         // cell ss rows I, I+1 (112)
    __shared__ float vbuf[NB * VSTRIDE];  // normalized blocks, padded stride

    const int b = blockIdx.x / NB;
    const int I = blockIdx.x % NB;
    const int tid = threadIdx.x;

    {
        const float4* src4 = (const float4*)(hist + ((size_t)b * NR + I) * NR * 9);
        if (tid < 252) ((float4*)sh)[tid] = src4[tid];
        const float* cs = cellss + ((size_t)b * NR + I) * NR;
        if (tid < 2 * NR) scs[tid] = cs[tid];
    }
    __syncthreads();

    const int w    = tid >> 5;
    const int lane = tid & 31;
    const int g    = lane & 3;            // cell within block
    const int J    = w + 8 * (lane >> 2); // block column (may be >= NB)
    const int Jc   = (J < NB) ? J : (NB - 1);  // clamped for safe reads

    float inv1 = rsqrtf(scs[Jc] + scs[Jc + 1] + scs[NR + Jc] + scs[NR + Jc + 1]
                        + 1e-10f);

    const float* cell = sh + (g >> 1) * (NR * 9) + (Jc + (g & 1)) * 9;
    float v[9];
    float ss = 0.f;
    #pragma unroll
    for (int k = 0; k < 9; k++) {
        float f = fminf(cell[k] * inv1, 0.2f);
        v[k] = f;
        ss = fmaf(f, f, ss);
    }
    ss += __shfl_xor_sync(0xffffffffu, ss, 1);
    ss += __shfl_xor_sync(0xffffffffu, ss, 2);
    float inv2 = rsqrtf(ss + 1e-10f);

    if (J < NB) {
        float* dst = vbuf + J * VSTRIDE + g * 9;
        #pragma unroll
        for (int k = 0; k < 9; k++) dst[k] = v[k] * inv2;
    }
    __syncthreads();

    float* obase = out + (size_t)blockIdx.x * (NB * 36);
    #pragma unroll
    for (int e = tid; e < NB * 36; e += K2_THREADS) {
        int Jx = e / 36;
        int r  = e - Jx * 36;
        obase[e] = vbuf[Jx * VSTRIDE + r];
    }
}

// ---------------------------------------------------------------------------
extern "C" void kernel_launch(void* const* d_in, const int* in_sizes, int n_in,
                              void* d_out, int out_size)
{
    const float* x      = (const float*)d_in[0];
    const float* coeffs = (const float*)d_in[1];
    float* out          = (float*)d_out;

    float *hist, *cellss;
    cudaGetSymbolAddress((void**)&hist, g_hist);
    cudaGetSymbolAddress((void**)&cellss, g_cellss);

    // Period-4 launch pattern so ncu (-s 5) captures hog_cells_kernel.
    noop_kernel<<<1, 1>>>();

    dim3 g1(NR, B);
    hog_cells_kernel<<<g1, CROP>>>(x, coeffs, hist, cellss);

    noop_kernel<<<1, 1>>>();

    hog_blocks_kernel<<<B * NB, K2_THREADS>>>(hist, cellss, out);
}

// round 14
// speedup vs baseline: 1.0473x; 1.0473x over previous
#include <cuda_runtime.h>
#include <cuda_bf16.h>
#include <math.h>

#define CROP 448
#define NR   56      // cells per side
#define NB   55      // blocks per side
#define B    48
#define IMG  512
#define TOP  32
#define QPR  112     // float4 quads per row (448/4)
#define SGW  456     // padded smem row width: col c at index c+4

// Cell histogram scratch: [b][cell_r][cell_c][bin]
__device__ float g_hist[(size_t)B * NR * NR * 9];
// Per-cell sum of squares: [b][cell_r][cell_c]
__device__ float g_cellss[(size_t)B * NR * NR];

__device__ __forceinline__ float fsqrt_approx(float x) {
    float r;
    asm("sqrt.approx.f32 %0, %1;" : "=f"(r) : "f"(x));
    return r;
}
__device__ __forceinline__ float frcp_approx(float x) {
    float r;
    asm("rcp.approx.f32 %0, %1;" : "=f"(r) : "f"(x));
    return r;
}

// ---------------------------------------------------------------------------
// Kernel 1: gray -> sqrt -> gradients -> per-cell prefix histograms (+cell ss)
// grid: (NR, B), block: 448 threads (one per crop column)
// Binning: w = cot(theta) = gc/gr (period-180 => no half-plane fold needed).
// gr==0 forces w=+inf so theta in {0,180} lands in bin 0 (ref: 180%180=0).
// ---------------------------------------------------------------------------
__global__ __launch_bounds__(CROP) void hog_cells_kernel(
    const float* __restrict__ x, const float* __restrict__ coeffs,
    float* __restrict__ hist, float* __restrict__ cellss)
{
    __shared__ float sg[10][SGW];

    const int cr = blockIdx.x;       // cell row 0..55
    const int b  = blockIdx.y;
    const int c  = threadIdx.x;      // crop column 0..447
    const int r0 = cr * 8;

    const float c0 = coeffs[0], c1 = coeffs[1], c2 = coeffs[2];
    const float* base = x + (size_t)b * 3 * IMG * IMG;

    // Stage 10 rows of sqrt(gray); reflection clamp makes boundary gr = 0.
    // Edge-column reflections written inline by quad-0 / quad-111 threads.
    #pragma unroll
    for (int e = c; e < 10 * QPR; e += CROP) {
        int i = e / QPR;
        int q = e - i * QPR;
        int r = r0 - 1 + i;
        if (r < 0) r = -r;                        // -1 -> 1
        if (r > CROP - 1) r = 2 * (CROP - 1) - r; // 448 -> 446
        const float4* p = (const float4*)(base + (size_t)(r + TOP) * IMG + TOP) + q;
        float4 a0 = p[0];
        float4 a1 = p[(IMG * IMG) / 4];
        float4 a2 = p[(2 * IMG * IMG) / 4];
        float4 g;
        g.x = fsqrt_approx(fmaf(c0, a0.x, fmaf(c1, a1.x, c2 * a2.x)));
        g.y = fsqrt_approx(fmaf(c0, a0.y, fmaf(c1, a1.y, c2 * a2.y)));
        g.z = fsqrt_approx(fmaf(c0, a0.z, fmaf(c1, a1.z, c2 * a2.z)));
        g.w = fsqrt_approx(fmaf(c0, a0.w, fmaf(c1, a1.w, c2 * a2.w)));
        *((float4*)&sg[i][4 + q * 4]) = g;
        if (q == 0)       sg[i][3]   = g.y;   // col -1  := col 1
        if (q == QPR - 1) sg[i][452] = g.z;   // col 448 := col 446
    }
    __syncthreads();

    // cot(20k degrees), k = 1..8
    const float KT[8] = { 2.7474774f,  1.1917536f,  0.57735027f,  0.17632698f,
                         -0.17632698f, -0.57735027f, -1.1917536f, -2.7474774f};
    const float INF = __int_as_float(0x7f800000);

    float vreg[10];
    #pragma unroll
    for (int i = 0; i < 10; i++) vreg[i] = sg[i][c + 4];

    // Prefix histogram: H[k] = sum of mag over pixels with angle >= 20k.
    float H[9];
    #pragma unroll
    for (int k = 0; k < 9; k++) H[k] = 0.f;

    #pragma unroll
    for (int i = 0; i < 8; i++) {
        float gr = vreg[i + 2] - vreg[i];
        float gc = sg[i + 1][c + 5] - sg[i + 1][c + 3];

        float mag = fsqrt_approx(fmaf(gr, gr, gc * gc));

        // w = cot(angle) = gc/gr; valid in both half-planes (period 180).
        // gr==0 (either sign) -> +inf -> bin 0, matching 180 % 180 = 0.
        // gr==0 && gc==0 -> forced +inf -> bin 0 with mag 0 (harmless).
        float w = gc * frcp_approx(gr);
        if (gr == 0.f) w = INF;

        H[0] += mag;
        #pragma unroll
        for (int k = 0; k < 8; k++)
            if (w <= KT[k]) H[k + 1] += mag;
    }

    #pragma unroll
    for (int k = 0; k < 9; k++) {
        H[k] += __shfl_xor_sync(0xffffffffu, H[k], 1);
        H[k] += __shfl_xor_sync(0xffffffffu, H[k], 2);
        H[k] += __shfl_xor_sync(0xffffffffu, H[k], 4);
    }

    if ((c & 7) == 0) {
        int cell = c >> 3;
        size_t cidx = ((size_t)b * NR + cr) * NR + cell;
        float ss = 0.f;
        #pragma unroll
        for (int k = 0; k < 9; k++) {
            float hk = ((k < 8) ? (H[k] - H[k + 1]) : H[8]) * (1.0f / 64.0f);
            hist[cidx * 9 + k] = hk;
            ss += hk * hk;
        }
        cellss[cidx] = ss;
    }
}

// ---------------------------------------------------------------------------
// Kernel 2: L2-Hys block normalization. One CTA per (b, I) block-row.
// [R7 version verbatim — best measured 12.0-12.3us, frozen]
// ---------------------------------------------------------------------------
#define K2_THREADS 256
#define VSTRIDE 37          // padded per-block stride in vbuf (kills conflicts)

__global__ __launch_bounds__(K2_THREADS) void hog_blocks_kernel(
    const float* __restrict__ hist, const float* __restrict__ cellss,
    float* __restrict__ out)
{
    __shared__ float sh[2 * NR * 9];      // hist rows I, I+1 (1008)
    __shared__ float scs[2 * NR];         // cell ss rows I, I+1 (112)
    __shared__ float vbuf[NB * VSTRIDE];  // normalized blocks, padded stride

    const int b = blockIdx.x / NB;
    const int I = blockIdx.x % NB;
    const int tid = threadIdx.x;

    {
        const float4* src4 = (const float4*)(hist + ((size_t)b * NR + I) * NR * 9);
        if (tid < 252) ((float4*)sh)[tid] = src4[tid];
        const float* cs = cellss + ((size_t)b * NR + I) * NR;
        if (tid < 2 * NR) scs[tid] = cs[tid];
    }
    __syncthreads();

    const int w    = tid >> 5;
    const int lane = tid & 31;
    const int g    = lane & 3;            // cell within block
    const int J    = w + 8 * (lane >> 2); // block column (may be >= NB)
    const int Jc   = (J < NB) ? J : (NB - 1);  // clamped for safe reads

    float inv1 = rsqrtf(scs[Jc] + scs[Jc + 1] + scs[NR + Jc] + scs[NR + Jc + 1]
                        + 1e-10f);

    const float* cell = sh + (g >> 1) * (NR * 9) + (Jc + (g & 1)) * 9;
    float v[9];
    float ss = 0.f;
    #pragma unroll
    for (int k = 0; k < 9; k++) {
        float f = fminf(cell[k] * inv1, 0.2f);
        v[k] = f;
        ss = fmaf(f, f, ss);
    }
    ss += __shfl_xor_sync(0xffffffffu, ss, 1);
    ss += __shfl_xor_sync(0xffffffffu, ss, 2);
    float inv2 = rsqrtf(ss + 1e-10f);

    if (J < NB) {
        float* dst = vbuf + J * VSTRIDE + g * 9;
        #pragma unroll
        for (int k = 0; k < 9; k++) dst[k] = v[k] * inv2;
    }
    __syncthreads();

    float* obase = out + (size_t)blockIdx.x * (NB * 36);
    #pragma unroll
    for (int e = tid; e < NB * 36; e += K2_THREADS) {
        int Jx = e / 36;
        int r  = e - Jx * 36;
        obase[e] = vbuf[Jx * VSTRIDE + r];
    }
}

// ---------------------------------------------------------------------------
extern "C" void kernel_launch(void* const* d_in, const int* in_sizes, int n_in,
                              void* d_out, int out_size)
{
    const float* x      = (const float*)d_in[0];
    const float* coeffs = (const float*)d_in[1];
    float* out          = (float*)d_out;

    float *hist, *cellss;
    cudaGetSymbolAddress((void**)&hist, g_hist);
    cudaGetSymbolAddress((void**)&cellss, g_cellss);

    dim3 g1(NR, B);
    hog_cells_kernel<<<g1, CROP>>>(x, coeffs, hist, cellss);

    hog_blocks_kernel<<<B * NB, K2_THREADS>>>(hist, cellss, out);
}